// round 11
// baseline (speedup 1.0000x reference)
#include <cuda_runtime.h>
#include <cuda_fp16.h>
#include <cstdint>

#define BATCH 32
#define C 512
#define HW 3136
#define HID 128
#define TILES 25
#define EPS_BN 1e-5f

#define PA 72        // W1 pitch (halves), 144B rows
#define PB 136       // X / h / W2 pitch (halves), 272B rows

#define NSTAGE 4
#define STAGE_BYTES 35840            // W part [0,18432) ; X part [18432,35840)
#define OFF_RING 1024
#define OFF_H (OFF_RING + NSTAGE*STAGE_BYTES)    // 144384
#define SMEM_BYTES (OFF_H + HID*PB*2)            // 179200 -> 1 CTA/SM, 24 warps

__device__ __align__(16) __half g_w1[2*HID*C];
__device__ __align__(16) __half g_w2[2*C*HID];
__device__ float g_ss[2*2*HID];

__global__ void prep_kernel(const float* __restrict__ w1r, const float* __restrict__ w1i,
                            const float* __restrict__ w2r, const float* __restrict__ w2i,
                            const float* __restrict__ rmr, const float* __restrict__ rvr,
                            const float* __restrict__ gr,  const float* __restrict__ bbr,
                            const float* __restrict__ rmi, const float* __restrict__ rvi,
                            const float* __restrict__ gi,  const float* __restrict__ bbi)
{
    int idx = blockIdx.x * blockDim.x + threadIdx.x;
    if (idx < HID * C) {
        g_w1[idx]         = __float2half_rn(w1r[idx]);
        g_w1[HID*C + idx] = __float2half_rn(w1i[idx]);
        g_w2[idx]         = __float2half_rn(w2r[idx]);
        g_w2[C*HID + idx] = __float2half_rn(w2i[idx]);
    }
    if (idx < HID) {
        float s0 = gr[idx] / sqrtf(rvr[idx] + EPS_BN);
        g_ss[idx]         = s0;
        g_ss[HID + idx]   = bbr[idx] - rmr[idx] * s0;
        float s1 = gi[idx] / sqrtf(rvi[idx] + EPS_BN);
        g_ss[2*HID + idx] = s1;
        g_ss[3*HID + idx] = bbi[idx] - rmi[idx] * s1;
    }
}

__device__ __forceinline__ void cp16(uint32_t dst_smem, const void* src) {
    asm volatile("cp.async.cg.shared.global [%0], [%1], 16;\n" :: "r"(dst_smem), "l"(src));
}
#define CP_COMMIT() asm volatile("cp.async.commit_group;\n" ::)
#define CP_WAIT0()  asm volatile("cp.async.wait_group 0;\n" ::)

__device__ __forceinline__ void ldsm4a(uint32_t r[4], uint32_t a) {
    asm volatile("ldmatrix.sync.aligned.m8n8.x4.shared.b16 {%0,%1,%2,%3}, [%4];"
                 : "=r"(r[0]), "=r"(r[1]), "=r"(r[2]), "=r"(r[3]) : "r"(a));
}
__device__ __forceinline__ void ldsm4ta(uint32_t r[4], uint32_t a) {
    asm volatile("ldmatrix.sync.aligned.m8n8.x4.trans.shared.b16 {%0,%1,%2,%3}, [%4];"
                 : "=r"(r[0]), "=r"(r[1]), "=r"(r[2]), "=r"(r[3]) : "r"(a));
}
__device__ __forceinline__ void mma_fp16(float d[4], const uint32_t a[4], uint32_t b0, uint32_t b1) {
    asm volatile("mma.sync.aligned.m16n8k16.row.col.f32.f16.f16.f32 "
                 "{%0,%1,%2,%3}, {%4,%5,%6,%7}, {%8,%9}, {%0,%1,%2,%3};"
                 : "+f"(d[0]), "+f"(d[1]), "+f"(d[2]), "+f"(d[3])
                 : "r"(a[0]), "r"(a[1]), "r"(a[2]), "r"(a[3]), "r"(b0), "r"(b1));
}
__device__ __forceinline__ void mbar_wait(uint32_t mb, uint32_t parity) {
    asm volatile(
        "{\n\t.reg .pred P1;\n\t"
        "WAIT_LOOP_%=:\n\t"
        "mbarrier.try_wait.parity.acquire.cta.shared::cta.b64 P1, [%0], %1, 0x989680;\n\t"
        "@P1 bra.uni WAIT_DONE_%=;\n\t"
        "bra.uni WAIT_LOOP_%=;\n\t"
        "WAIT_DONE_%=:\n\t}"
        :: "r"(mb), "r"(parity) : "memory");
}
#define MBAR_INIT(mb, n)  asm volatile("mbarrier.init.shared.b64 [%0], %1;" :: "r"(mb), "r"(n) : "memory")
#define MBAR_ARRIVE(mb)   asm volatile("mbarrier.arrive.shared.b64 _, [%0];" :: "r"(mb) : "memory")

__global__ __launch_bounds__(768, 1)
void fused_kernel(const float* __restrict__ x, const int* __restrict__ mod,
                  float* __restrict__ out)
{
    extern __shared__ __align__(16) __half smem[];
    const uint32_t sb = (uint32_t)__cvta_generic_to_shared(smem);
    __half* sH = smem + OFF_H / 2;

    const int tid  = threadIdx.x;
    const int warp = tid >> 5, lane = tid & 31;
    const int bimg = blockIdx.x / TILES;
    const int tile = blockIdx.x % TILES;
    const int p0   = tile * 128;
    const int br   = (__ldg(&mod[bimg]) == 1) ? 0 : 1;

    const float* xb = x   + (size_t)bimg * C * HW;
    float*       ob = out + (size_t)bimg * C * HW;
    const __half* w1 = g_w1 + br * HID * C;
    const __half* w2 = g_w2 + br * C * HID;

    // mbarrier ring: full[s] @ sb+16s, empty[s] @ sb+16s+8
    if (tid == 0) {
        #pragma unroll
        for (int s = 0; s < NSTAGE; s++) {
            MBAR_INIT(sb + s * 16, 128);       // full: one producer half-group
            MBAR_INIT(sb + s * 16 + 8, 512);   // empty: all consumers
        }
    }
    __syncthreads();

    if (warp >= 16) {
        // ================= PRODUCERS (warps 16..23) =================
        const int ptid = tid - 512;            // 0..255
        const int half = ptid >> 7;            // stage parity this half serves
        const int pt   = ptid & 127;

        for (int s = half; s < 12; s += 2) {
            const uint32_t stg = sb + OFF_RING + (s & 3) * STAGE_BYTES;
            if (s >= NSTAGE)
                mbar_wait(sb + (s & 3) * 16 + 8, ((s - NSTAGE) >> 2) & 1);
            if (s < 8) {
                // ---- phase A stage: W1 chunk + X chunk ----
                const int kc = s * 64;
                #pragma unroll
                for (int t = 0; t < 8; t++) {      // W1: 128 rows x 64 halves
                    int idx = pt + t * 128;
                    int r = idx >> 3, u = idx & 7;
                    cp16(stg + (r * PA + u * 8) * 2, w1 + r * C + kc + u * 8);
                }
                CP_COMMIT();
                // X: 64 ch-rows x 128 px, fp32 -> fp16 (2 batches of 8 float4)
                #pragma unroll
                for (int b = 0; b < 2; b++) {
                    float4 xv[8];
                    #pragma unroll
                    for (int t = 0; t < 8; t++) {
                        int idx = pt + (b * 8 + t) * 128;
                        int row = idx >> 5;
                        int pg  = (idx & 31) << 2;
                        int gp  = p0 + pg; if (gp > HW - 4) gp = HW - 4;
                        xv[t] = *(const float4*)(xb + (size_t)(kc + row) * HW + gp);
                    }
                    #pragma unroll
                    for (int t = 0; t < 8; t++) {
                        int idx = pt + (b * 8 + t) * 128;
                        int row = idx >> 5;
                        int pg  = (idx & 31) << 2;
                        __half2 h0 = __floats2half2_rn(xv[t].x, xv[t].y);
                        __half2 h1 = __floats2half2_rn(xv[t].z, xv[t].w);
                        uint2 pk;
                        pk.x = *reinterpret_cast<uint32_t*>(&h0);
                        pk.y = *reinterpret_cast<uint32_t*>(&h1);
                        *(uint2*)(smem + (stg - sb + 18432) / 2 + row * PB + pg) = pk;
                    }
                }
                CP_WAIT0();
            } else {
                // ---- phase B stage: W2 chunk (128 out-ch x 128 k) ----
                const int cc = (s - 8) * 128;
                #pragma unroll
                for (int t = 0; t < 16; t++) {
                    int idx = pt + t * 128;
                    int r = idx >> 4, u = idx & 15;
                    cp16(stg + (r * PB + u * 8) * 2, w2 + (size_t)(cc + r) * HID + u * 8);
                }
                CP_COMMIT(); CP_WAIT0();
            }
            MBAR_ARRIVE(sb + (s & 3) * 16);    // full
        }
        return;   // producers done; no __syncthreads below
    }

    // ================= CONSUMERS (warps 0..15) =================
    const int wr3 = warp >> 2, wc3 = warp & 3;     // 4x4 grid of 32x32 tiles
    const int g  = lane >> 2, tg = lane & 3;
    const int l16 = lane & 15, lh = lane >> 4;

    float acc[2][4][4];
    #pragma unroll
    for (int a = 0; a < 2; a++)
        #pragma unroll
        for (int b2 = 0; b2 < 4; b2++)
            #pragma unroll
            for (int c2 = 0; c2 < 4; c2++) acc[a][b2][c2] = 0.f;

    // ---- Phase A: D1[128 hid x 128 px] = W1 . X, 8 stages of K=64 ----
    for (int s = 0; s < 8; s++) {
        mbar_wait(sb + (s & 3) * 16, (s >> 2) & 1);
        const uint32_t wb = sb + OFF_RING + (s & 3) * STAGE_BYTES;
        const uint32_t xbuf = wb + 18432;
        #pragma unroll
        for (int ks = 0; ks < 64; ks += 16) {
            uint32_t Af[2][4];
            #pragma unroll
            for (int mf = 0; mf < 2; mf++)
                ldsm4a(Af[mf], wb + ((32*wr3 + 16*mf + l16) * PA + ks + 8*lh) * 2);
            uint32_t Bf[2][4];
            #pragma unroll
            for (int nf = 0; nf < 2; nf++)
                ldsm4ta(Bf[nf], xbuf + ((ks + l16) * PB + 32*wc3 + 16*nf + 8*lh) * 2);
            #pragma unroll
            for (int mf = 0; mf < 2; mf++)
                #pragma unroll
                for (int nf = 0; nf < 2; nf++) {
                    mma_fp16(acc[mf][nf*2 + 0], Af[mf], Bf[nf][0], Bf[nf][1]);
                    mma_fp16(acc[mf][nf*2 + 1], Af[mf], Bf[nf][2], Bf[nf][3]);
                }
        }
        MBAR_ARRIVE(sb + (s & 3) * 16 + 8);    // empty
    }

    // ---- Epilogue A: BN + ReLU -> fp16 h in sH ----
    #pragma unroll
    for (int mf = 0; mf < 2; mf++)
        #pragma unroll
        for (int rh = 0; rh < 2; rh++) {
            int row = 32*wr3 + 16*mf + 8*rh + g;
            float sc = g_ss[br*2*HID + row];
            float sh = g_ss[br*2*HID + HID + row];
            #pragma unroll
            for (int nf = 0; nf < 2; nf++)
                #pragma unroll
                for (int hh = 0; hh < 2; hh++) {
                    int col = 32*wc3 + 16*nf + 8*hh + 2*tg;
                    float v0 = fmaxf(fmaf(acc[mf][nf*2+hh][2*rh+0], sc, sh), 0.f);
                    float v1 = fmaxf(fmaf(acc[mf][nf*2+hh][2*rh+1], sc, sh), 0.f);
                    *(__half2*)&sH[row * PB + col] = __floats2half2_rn(v0, v1);
                }
        }
    asm volatile("bar.sync 1, %0;" :: "r"(512) : "memory");   // consumers only

    // ---- Phase B: out = W2 . h, 4 stages of 128 output channels ----
    for (int s = 8; s < 12; s++) {
        mbar_wait(sb + (s & 3) * 16, (s >> 2) & 1);
        const uint32_t wb = sb + OFF_RING + (s & 3) * STAGE_BYTES;
        const uint32_t hb = sb + OFF_H;

        #pragma unroll
        for (int a = 0; a < 2; a++)
            #pragma unroll
            for (int b2 = 0; b2 < 4; b2++)
                #pragma unroll
                for (int c2 = 0; c2 < 4; c2++) acc[a][b2][c2] = 0.f;

        #pragma unroll
        for (int ks = 0; ks < 128; ks += 16) {
            uint32_t Af[2][4];
            #pragma unroll
            for (int mf = 0; mf < 2; mf++)
                ldsm4a(Af[mf], wb + ((32*wr3 + 16*mf + l16) * PB + ks + 8*lh) * 2);
            uint32_t Bf[2][4];
            #pragma unroll
            for (int nf = 0; nf < 2; nf++)
                ldsm4ta(Bf[nf], hb + ((ks + l16) * PB + 32*wc3 + 16*nf + 8*lh) * 2);
            #pragma unroll
            for (int mf = 0; mf < 2; mf++)
                #pragma unroll
                for (int nf = 0; nf < 2; nf++) {
                    mma_fp16(acc[mf][nf*2 + 0], Af[mf], Bf[nf][0], Bf[nf][1]);
                    mma_fp16(acc[mf][nf*2 + 1], Af[mf], Bf[nf][2], Bf[nf][3]);
                }
        }
        MBAR_ARRIVE(sb + (s & 3) * 16 + 8);    // empty (W2 chunk consumed)

        // store: channels (s-8)*128 + warp rows, px tile cols
        const int cc = (s - 8) * 128;
        #pragma unroll
        for (int mf = 0; mf < 2; mf++)
            #pragma unroll
            for (int rh = 0; rh < 2; rh++) {
                int row = cc + 32*wr3 + 16*mf + 8*rh + g;
                #pragma unroll
                for (int nf = 0; nf < 2; nf++)
                    #pragma unroll
                    for (int hh = 0; hh < 2; hh++) {
                        int col = 32*wc3 + 16*nf + 8*hh + 2*tg;
                        if (p0 + col < HW) {
                            float2 v = make_float2(acc[mf][nf*2+hh][2*rh+0],
                                                   acc[mf][nf*2+hh][2*rh+1]);
                            *(float2*)&ob[(size_t)row * HW + p0 + col] = v;
                        }
                    }
            }
    }
}

extern "C" void kernel_launch(void* const* d_in, const int* in_sizes, int n_in,
                              void* d_out, int out_size)
{
    (void)in_sizes; (void)n_in; (void)out_size;
    const float* x   = (const float*)d_in[0];
    const int*   md  = (const int*)  d_in[1];
    const float* w1r = (const float*)d_in[2];
    const float* rmr = (const float*)d_in[3];
    const float* rvr = (const float*)d_in[4];
    const float* gr  = (const float*)d_in[5];
    const float* bbr = (const float*)d_in[6];
    const float* w2r = (const float*)d_in[7];
    const float* w1i = (const float*)d_in[8];
    const float* rmi = (const float*)d_in[9];
    const float* rvi = (const float*)d_in[10];
    const float* gi  = (const float*)d_in[11];
    const float* bbi = (const float*)d_in[12];
    const float* w2i = (const float*)d_in[13];
    float* out = (float*)d_out;

    cudaFuncSetAttribute(fused_kernel, cudaFuncAttributeMaxDynamicSharedMemorySize, SMEM_BYTES);

    prep_kernel<<<(HID * C + 255) / 256, 256>>>(w1r, w1i, w2r, w2i,
                                                rmr, rvr, gr, bbr,
                                                rmi, rvi, gi, bbi);
    fused_kernel<<<BATCH * TILES, 768, SMEM_BYTES>>>(x, md, out);
}